// round 17
// baseline (speedup 1.0000x reference)
#include <cuda_runtime.h>
#include <cuda_bf16.h>
#include <cstdint>
#include <cstddef>

#define N_NODES 100000
#define N_EDGES 1600000
#define D 128
#define BM 128
#define MROWS 100096      // 782*128 padded row count
#define NTILES 782
#define NPCTA 152         // persistent CTAs (GB300: 152 SMs)
#define SCAN_BLK 391      // ceil(100000/256)
#define MLP_THREADS 512

// ---------------------------------------------------------------------------
// Device-global scratch (allocation-free rules; zero-init at load; pad rows of
// the plane buffers are never written -> stay zero).
// ---------------------------------------------------------------------------
__device__ int g_deg[N_NODES];
__device__ int g_off[N_NODES];
__device__ int g_cur[N_NODES];
__device__ int g_bsum[SCAN_BLK];
__device__ int g_bpre[SCAN_BLK];
__device__ int g_csr[N_EDGES];
__device__ uint32_t g_a1h[(size_t)MROWS * 64];   // A_eff hi plane (bf16 pairs)
__device__ uint32_t g_a1l[(size_t)MROWS * 64];   // A_eff lo plane
__device__ __nv_bfloat16 g_wbh[2][D * D];        // W^T hi [n][k]
__device__ __nv_bfloat16 g_wbl[2][D * D];        // W^T lo [n][k]

// ---------------------------------------------------------------------------
// Helpers
// ---------------------------------------------------------------------------
__device__ __forceinline__ uint32_t smem_u32(const void* p) {
    uint32_t a;
    asm("{ .reg .u64 t; cvta.to.shared.u64 t, %1; cvt.u32.u64 %0, t; }"
        : "=r"(a) : "l"(p));
    return a;
}
__device__ __forceinline__ uint32_t pack_bf2(float a, float b) {
    uint16_t ua = __bfloat16_as_ushort(__float2bfloat16(a));
    uint16_t ub = __bfloat16_as_ushort(__float2bfloat16(b));
    return (uint32_t)ua | ((uint32_t)ub << 16);
}
__device__ __forceinline__ float bf_res(float v) {
    return v - __bfloat162float(__float2bfloat16(v));
}
__device__ __forceinline__ void ldm4(uint32_t& r0, uint32_t& r1,
                                     uint32_t& r2, uint32_t& r3, uint32_t addr) {
    asm volatile("ldmatrix.sync.aligned.m8n8.x4.shared.b16 {%0,%1,%2,%3}, [%4];"
                 : "=r"(r0), "=r"(r1), "=r"(r2), "=r"(r3) : "r"(addr));
}
__device__ __forceinline__ void mma_bf16(float* c, const uint32_t* a,
                                         const uint32_t* b) {
    asm volatile(
        "mma.sync.aligned.m16n8k16.row.col.f32.bf16.bf16.f32 "
        "{%0,%1,%2,%3}, {%4,%5,%6,%7}, {%8,%9}, {%0,%1,%2,%3};"
        : "+f"(c[0]), "+f"(c[1]), "+f"(c[2]), "+f"(c[3])
        : "r"(a[0]), "r"(a[1]), "r"(a[2]), "r"(a[3]), "r"(b[0]), "r"(b[1]));
}
__device__ __forceinline__ void cpa16(uint32_t dst, const void* src) {
    asm volatile("cp.async.cg.shared.global [%0], [%1], 16;"
                 :: "r"(dst), "l"(src));
}
#define CP_COMMIT() asm volatile("cp.async.commit_group;" ::: "memory")
#define CP_WAIT0()  asm volatile("cp.async.wait_group 0;" ::: "memory")

// ---------------------------------------------------------------------------
// prep: split W into bf16 hi/lo, transposed to [n][k].
// ---------------------------------------------------------------------------
__global__ void prep_w(const float* __restrict__ W1, const float* __restrict__ W2) {
    int idx = blockIdx.x * blockDim.x + threadIdx.x;
    int which = blockIdx.y;
    const float* W = which ? W2 : W1;
    int k = idx >> 7, n = idx & 127;
    float v = __ldg(&W[k * D + n]);
    g_wbh[which][n * D + k] = __float2bfloat16(v);
    g_wbl[which][n * D + k] = __float2bfloat16(bf_res(v));
}

// ---------------------------------------------------------------------------
// CSR build: zero -> hist -> 3-phase parallel scan -> fill (int4-vectorized)
// ---------------------------------------------------------------------------
__global__ void zero_deg() {
    int i = blockIdx.x * blockDim.x + threadIdx.x;
    if (i < N_NODES / 4) ((int4*)g_deg)[i] = make_int4(0, 0, 0, 0);
    // N_NODES = 100000 = 4*25000, exact
}
__global__ void hist_kernel(const int* __restrict__ ei) {
    int i = blockIdx.x * blockDim.x + threadIdx.x;   // 0..N_EDGES/4-1
    if (i >= N_EDGES / 4) return;
    int4 d = __ldg((const int4*)(ei + N_EDGES) + i);
    atomicAdd(&g_deg[d.x], 1);
    atomicAdd(&g_deg[d.y], 1);
    atomicAdd(&g_deg[d.z], 1);
    atomicAdd(&g_deg[d.w], 1);
}
__global__ void scan1_kernel() {
    __shared__ int s[256];
    int tid = threadIdx.x;
    int i = blockIdx.x * 256 + tid;
    int v = (i < N_NODES) ? g_deg[i] : 0;
    s[tid] = v;
    __syncthreads();
    #pragma unroll
    for (int d = 1; d < 256; d <<= 1) {
        int t = (tid >= d) ? s[tid - d] : 0;
        __syncthreads();
        s[tid] += t;
        __syncthreads();
    }
    if (i < N_NODES) g_off[i] = s[tid] - v;
    if (tid == 255) g_bsum[blockIdx.x] = s[255];
}
__global__ void scan2_kernel() {
    __shared__ int s[512];
    int tid = threadIdx.x;
    int v = (tid < SCAN_BLK) ? g_bsum[tid] : 0;
    s[tid] = v;
    __syncthreads();
    #pragma unroll
    for (int d = 1; d < 512; d <<= 1) {
        int t = (tid >= d) ? s[tid - d] : 0;
        __syncthreads();
        s[tid] += t;
        __syncthreads();
    }
    if (tid < SCAN_BLK) g_bpre[tid] = s[tid] - v;
}
__global__ void scan3_kernel() {
    int i = blockIdx.x * 256 + threadIdx.x;
    if (i < N_NODES) {
        int o = g_off[i] + g_bpre[blockIdx.x];
        g_off[i] = o;
        g_cur[i] = o;
    }
}
__global__ void fill_kernel(const int* __restrict__ ei) {
    int i = blockIdx.x * blockDim.x + threadIdx.x;   // 0..N_EDGES/4-1
    if (i >= N_EDGES / 4) return;
    int4 s = __ldg((const int4*)ei + i);
    int4 d = __ldg((const int4*)(ei + N_EDGES) + i);
    g_csr[atomicAdd(&g_cur[d.x], 1)] = s.x;
    g_csr[atomicAdd(&g_cur[d.y], 1)] = s.y;
    g_csr[atomicAdd(&g_cur[d.z], 1)] = s.z;
    g_csr[atomicAdd(&g_cur[d.w], 1)] = s.w;
}

// ---------------------------------------------------------------------------
// Gather + GIN combine + bf16 split: one warp per node, 4-way MLP unroll.
// ---------------------------------------------------------------------------
__global__ void gather_kernel(const float* __restrict__ x,
                              const float* __restrict__ epsp) {
    int gw = (blockIdx.x * blockDim.x + threadIdx.x) >> 5;
    int lane = threadIdx.x & 31;
    if (gw >= N_NODES) return;
    float scale = 1.0f + __ldg(epsp);
    const float4* xb = (const float4*)x;

    float4 v = __ldg(&xb[(size_t)gw * 32 + lane]);
    float4 a0 = make_float4(scale * v.x, scale * v.y, scale * v.z, scale * v.w);
    float4 a1 = make_float4(0.f, 0.f, 0.f, 0.f);
    float4 a2 = a1, a3 = a1;

    const int base = g_off[gw];
    const int deg  = g_deg[gw];
    int c = 0;
    for (; c + 4 <= deg; c += 4) {
        int s0 = __ldg(&g_csr[base + c + 0]);
        int s1 = __ldg(&g_csr[base + c + 1]);
        int s2 = __ldg(&g_csr[base + c + 2]);
        int s3 = __ldg(&g_csr[base + c + 3]);
        float4 w0 = __ldg(&xb[(size_t)s0 * 32 + lane]);
        float4 w1 = __ldg(&xb[(size_t)s1 * 32 + lane]);
        float4 w2 = __ldg(&xb[(size_t)s2 * 32 + lane]);
        float4 w3 = __ldg(&xb[(size_t)s3 * 32 + lane]);
        a0.x += w0.x; a0.y += w0.y; a0.z += w0.z; a0.w += w0.w;
        a1.x += w1.x; a1.y += w1.y; a1.z += w1.z; a1.w += w1.w;
        a2.x += w2.x; a2.y += w2.y; a2.z += w2.z; a2.w += w2.w;
        a3.x += w3.x; a3.y += w3.y; a3.z += w3.z; a3.w += w3.w;
    }
    for (; c < deg; c++) {
        int s0 = __ldg(&g_csr[base + c]);
        float4 w0 = __ldg(&xb[(size_t)s0 * 32 + lane]);
        a0.x += w0.x; a0.y += w0.y; a0.z += w0.z; a0.w += w0.w;
    }
    float4 acc;
    acc.x = (a0.x + a1.x) + (a2.x + a3.x);
    acc.y = (a0.y + a1.y) + (a2.y + a3.y);
    acc.z = (a0.z + a1.z) + (a2.z + a3.z);
    acc.w = (a0.w + a1.w) + (a2.w + a3.w);

    uint2 hu, lu;
    hu.x = pack_bf2(acc.x, acc.y);
    hu.y = pack_bf2(acc.z, acc.w);
    lu.x = pack_bf2(bf_res(acc.x), bf_res(acc.y));
    lu.y = pack_bf2(bf_res(acc.z), bf_res(acc.w));
    ((uint2*)g_a1h)[(size_t)gw * 32 + lane] = hu;
    ((uint2*)g_a1l)[(size_t)gw * 32 + lane] = lu;
}

// ---------------------------------------------------------------------------
// Fused persistent 2-layer MLP GEMM (bf16x3 split, tensor cores).
// 512 threads = 16 warps in 4m x 4n (warp tile 32x32): 4 warps/SMSP for
// latency hiding. W1/W2 planes + biases staged once. Per row-tile:
//   cp.async A hi/lo planes; GEMM1; +b1, relu -> h planes in-place; GEMM2;
//   +b2 -> fp32 out.
// ---------------------------------------------------------------------------
#define PL 272
#define WPLANE (128 * PL)                  // 34816
#define SM_W1H 1024
#define SM_W1L (SM_W1H + WPLANE)
#define SM_W2H (SM_W1L + WPLANE)
#define SM_W2L (SM_W2H + WPLANE)
#define SM_A   (SM_W2L + WPLANE)           // A/h stage: hi plane then lo plane
#define SMEM_TOT (SM_A + 2 * WPLANE)       // 209920

__global__ void __launch_bounds__(MLP_THREADS, 1)
gin_mlp_persist(const uint32_t* __restrict__ Ah, const uint32_t* __restrict__ Al,
                const __nv_bfloat16* __restrict__ W1h,
                const __nv_bfloat16* __restrict__ W1l,
                const __nv_bfloat16* __restrict__ W2h,
                const __nv_bfloat16* __restrict__ W2l,
                const float* __restrict__ b1, const float* __restrict__ b2,
                float* __restrict__ out, int n_rows) {
    extern __shared__ char sm[];
    const int tid = threadIdx.x;
    const uint32_t sbase = smem_u32(sm);

    // ---- Stage biases + 4 W planes (once per CTA) ----
    float* sb_b1 = (float*)sm;
    float* sb_b2 = (float*)(sm + 512);
    if (tid < 128) {
        sb_b1[tid] = __ldg(&b1[tid]);
        sb_b2[tid] = __ldg(&b2[tid]);
    }
    {
        const uint4* srcs[4] = {(const uint4*)W1h, (const uint4*)W1l,
                                (const uint4*)W2h, (const uint4*)W2l};
        char* dsts[4] = {sm + SM_W1H, sm + SM_W1L, sm + SM_W2H, sm + SM_W2L};
        #pragma unroll
        for (int p = 0; p < 4; p++) {
            #pragma unroll
            for (int i = 0; i < 4; i++) {
                int idx = tid + i * MLP_THREADS;   // 0..2047 uint4s
                int n = idx >> 4, c16 = idx & 15;
                *(uint4*)(dsts[p] + n * PL + c16 * 16) = __ldg(&srcs[p][idx]);
            }
        }
    }

    // ---- ldmatrix lane addressing: 16 warps, wm=wid&3 (rows), wn=wid>>2 ----
    const int wid = tid >> 5, lane = tid & 31;
    const int wm = wid & 3, wn = wid >> 2;           // wn in 0..3, 32 cols each
    const int i8 = lane & 7;
    const int jA_m = ((lane >> 3) & 1) * 8;
    const int jA_k = (lane >> 4) * 8;
    const uint32_t aoff = (uint32_t)(wm * 32 + jA_m + i8) * PL + jA_k * 2;
    const uint32_t aH0 = sbase + SM_A + aoff;
    const uint32_t aH1 = aH0 + 16 * PL;
    const uint32_t aL0 = aH0 + WPLANE;
    const uint32_t aL1 = aL0 + 16 * PL;
    const int jB_k = ((lane >> 3) & 1) * 8;
    const int jB_n = (lane >> 4) * 8;
    uint32_t bW[2];
    #pragma unroll
    for (int g = 0; g < 2; g++) {
        uint32_t nrow = (uint32_t)(wn * 32 + g * 16 + jB_n + i8);
        bW[g] = sbase + SM_W1H + nrow * PL + jB_k * 2;
    }
    const int tig = lane & 3, grp = lane >> 2;

    auto gemm3 = [&](uint32_t bhi_off, uint32_t blo_off, float acc[2][4][4]) {
        #pragma unroll
        for (int m = 0; m < 2; m++)
            #pragma unroll
            for (int n = 0; n < 4; n++)
                #pragma unroll
                for (int q = 0; q < 4; q++) acc[m][n][q] = 0.f;
        #pragma unroll
        for (int ks = 0; ks < 8; ks++) {
            const uint32_t ko = ks * 32;
            uint32_t ah[2][4], al[2][4], bh[4][2], bl[4][2];
            ldm4(ah[0][0], ah[0][1], ah[0][2], ah[0][3], aH0 + ko);
            ldm4(ah[1][0], ah[1][1], ah[1][2], ah[1][3], aH1 + ko);
            ldm4(al[0][0], al[0][1], al[0][2], al[0][3], aL0 + ko);
            ldm4(al[1][0], al[1][1], al[1][2], al[1][3], aL1 + ko);
            #pragma unroll
            for (int g = 0; g < 2; g++) {
                ldm4(bh[2 * g][0], bh[2 * g][1], bh[2 * g + 1][0],
                     bh[2 * g + 1][1], bW[g] + bhi_off + ko);
                ldm4(bl[2 * g][0], bl[2 * g][1], bl[2 * g + 1][0],
                     bl[2 * g + 1][1], bW[g] + blo_off + ko);
            }
            #pragma unroll
            for (int n = 0; n < 4; n++) {
                #pragma unroll
                for (int m = 0; m < 2; m++) {
                    mma_bf16(acc[m][n], ah[m], bh[n]);
                    mma_bf16(acc[m][n], ah[m], bl[n]);
                    mma_bf16(acc[m][n], al[m], bh[n]);
                }
            }
        }
    };

    for (int t = blockIdx.x; t < NTILES; t += gridDim.x) {
        // ---- Load A hi/lo planes for this tile (pure cp.async copy) ----
        {
            const uint4* ah4 = (const uint4*)(Ah + (size_t)t * BM * 64);
            const uint4* al4 = (const uint4*)(Al + (size_t)t * BM * 64);
            uint32_t dst = sbase + SM_A;
            #pragma unroll
            for (int i = 0; i < 4; i++) {
                int idx = tid + i * MLP_THREADS;   // 0..2047
                int row = idx >> 4, c16 = idx & 15;
                uint32_t o = (uint32_t)(row * PL + c16 * 16);
                cpa16(dst + o, &ah4[idx]);
                cpa16(dst + WPLANE + o, &al4[idx]);
            }
            CP_COMMIT();
            CP_WAIT0();
        }
        __syncthreads();

        // ---- GEMM1: h = relu(A@W1 + b1) ----
        float acc[2][4][4];
        gemm3(0, (uint32_t)(SM_W1L - SM_W1H), acc);
        __syncthreads();

        // ---- Write h planes into the A stage ----
        #pragma unroll
        for (int m = 0; m < 2; m++) {
            int rl = wm * 32 + m * 16 + grp;
            #pragma unroll
            for (int n = 0; n < 4; n++) {
                int col = wn * 32 + n * 8 + tig * 2;
                float v0 = fmaxf(acc[m][n][0] + sb_b1[col], 0.f);
                float v1 = fmaxf(acc[m][n][1] + sb_b1[col + 1], 0.f);
                float v2 = fmaxf(acc[m][n][2] + sb_b1[col], 0.f);
                float v3 = fmaxf(acc[m][n][3] + sb_b1[col + 1], 0.f);
                char* hi0 = sm + SM_A + rl * PL + col * 2;
                *(uint32_t*)hi0 = pack_bf2(v0, v1);
                *(uint32_t*)(hi0 + WPLANE) = pack_bf2(bf_res(v0), bf_res(v1));
                char* hi1 = hi0 + 8 * PL;
                *(uint32_t*)hi1 = pack_bf2(v2, v3);
                *(uint32_t*)(hi1 + WPLANE) = pack_bf2(bf_res(v2), bf_res(v3));
            }
        }
        __syncthreads();

        // ---- GEMM2: out = h@W2 + b2 ----
        gemm3((uint32_t)(SM_W2H - SM_W1H), (uint32_t)(SM_W2L - SM_W1H), acc);

        const int row0 = t * BM;
        #pragma unroll
        for (int m = 0; m < 2; m++) {
            int r = row0 + wm * 32 + m * 16 + grp;
            #pragma unroll
            for (int n = 0; n < 4; n++) {
                int col = wn * 32 + n * 8 + tig * 2;
                float b0 = sb_b2[col], b1v = sb_b2[col + 1];
                if (r < n_rows)
                    *(float2*)(out + (size_t)r * D + col) =
                        make_float2(acc[m][n][0] + b0, acc[m][n][1] + b1v);
                if (r + 8 < n_rows)
                    *(float2*)(out + (size_t)(r + 8) * D + col) =
                        make_float2(acc[m][n][2] + b0, acc[m][n][3] + b1v);
            }
        }
        __syncthreads();
    }
}

// ---------------------------------------------------------------------------
extern "C" void kernel_launch(void* const* d_in, const int* in_sizes, int n_in,
                              void* d_out, int out_size) {
    const float* x   = (const float*)d_in[0];
    const int*   ei  = (const int*)d_in[1];
    const float* eps = (const float*)d_in[2];
    const float* W1  = (const float*)d_in[3];
    const float* b1  = (const float*)d_in[4];
    const float* W2  = (const float*)d_in[5];
    const float* b2  = (const float*)d_in[6];
    float*       out = (float*)d_out;

    uint32_t *a1h, *a1l;
    __nv_bfloat16 *wbh, *wbl;
    cudaGetSymbolAddress((void**)&a1h, g_a1h);
    cudaGetSymbolAddress((void**)&a1l, g_a1l);
    cudaGetSymbolAddress((void**)&wbh, g_wbh);
    cudaGetSymbolAddress((void**)&wbl, g_wbl);

    cudaFuncSetAttribute(gin_mlp_persist,
                         cudaFuncAttributeMaxDynamicSharedMemorySize, SMEM_TOT);

    // W split/transpose
    prep_w<<<dim3(64, 2), 256>>>(W1, W2);

    // CSR build (vectorized + parallel scan)
    zero_deg<<<(N_NODES / 4 + 255) / 256, 256>>>();
    hist_kernel<<<(N_EDGES / 4 + 255) / 256, 256>>>(ei);
    scan1_kernel<<<SCAN_BLK, 256>>>();
    scan2_kernel<<<1, 512>>>();
    scan3_kernel<<<SCAN_BLK, 256>>>();
    fill_kernel<<<(N_EDGES / 4 + 255) / 256, 256>>>(ei);

    // A_eff = (1+eps)x + gather  -> bf16 hi/lo planes
    gather_kernel<<<(N_NODES * 32 + 255) / 256, 256>>>(x, eps);

    // out = (relu(A_eff @ W1 + b1)) @ W2 + b2
    gin_mlp_persist<<<NPCTA, MLP_THREADS, SMEM_TOT>>>(
        a1h, a1l, wbh, wbl, wbh + D * D, wbl + D * D, b1, b2, out, N_NODES);
}